// round 6
// baseline (speedup 1.0000x reference)
#include <cuda_runtime.h>
#include <cuda_bf16.h>
#include <cstdint>
#include <math.h>

#define TOK 16384
#define HID 512
#define FF  2048
#define NE  8
#define ROWCAP (TOK*2 + NE*128)

typedef unsigned long long u64;

// ---------------- device scratch (no allocations allowed) ----------------
__device__ int   g_cnt[NE];
__device__ int   g_off[NE];
__device__ int   g_list[NE][TOK];
__device__ float g_wt[NE][TOK];

__device__ __nv_bfloat16 g_a_hi[(size_t)ROWCAP * HID];
__device__ __nv_bfloat16 g_a_lo[(size_t)ROWCAP * HID];
__device__ __nv_bfloat16 g_h_hi[(size_t)ROWCAP * FF];
__device__ __nv_bfloat16 g_h_lo[(size_t)ROWCAP * FF];
__device__ __nv_bfloat16 g_w1_hi[(size_t)NE * FF * HID];  // [e][n(FF)][k(HID)]
__device__ __nv_bfloat16 g_w1_lo[(size_t)NE * FF * HID];
__device__ __nv_bfloat16 g_w2_hi[(size_t)NE * HID * FF];  // [e][n(HID)][k(FF)]
__device__ __nv_bfloat16 g_w2_lo[(size_t)NE * HID * FF];

// ---------------- helpers ----------------
__device__ __forceinline__ uint32_t smem_u32(const void* p) {
    uint32_t a;
    asm("{ .reg .u64 t; cvta.to.shared.u64 t, %1; cvt.u32.u64 %0, t; }" : "=r"(a) : "l"(p));
    return a;
}
#define SWZ(x) ((x) ^ (((x) >> 3) & 0x70))

__device__ __forceinline__ void cp16(uint32_t dst, const void* src) {
    asm volatile("cp.async.cg.shared.global [%0], [%1], 16;" :: "r"(dst), "l"(src));
}
__device__ __forceinline__ void ldsm_x4(uint32_t& r0, uint32_t& r1, uint32_t& r2, uint32_t& r3,
                                        uint32_t addr) {
    asm volatile("ldmatrix.sync.aligned.m8n8.x4.shared.b16 {%0,%1,%2,%3}, [%4];"
                 : "=r"(r0), "=r"(r1), "=r"(r2), "=r"(r3) : "r"(addr));
}
__device__ __forceinline__ void mma16816(float* d, const uint32_t* a, uint32_t b0, uint32_t b1) {
    asm volatile("mma.sync.aligned.m16n8k16.row.col.f32.bf16.bf16.f32 "
                 "{%0,%1,%2,%3},{%4,%5,%6,%7},{%8,%9},{%0,%1,%2,%3};"
                 : "+f"(d[0]), "+f"(d[1]), "+f"(d[2]), "+f"(d[3])
                 : "r"(a[0]), "r"(a[1]), "r"(a[2]), "r"(a[3]), "r"(b0), "r"(b1));
}
__device__ __forceinline__ float gelu_f(float v) {
    float u = 1.5957691216057308f * (v + 0.044715f * v * v * v);
    return v / (1.0f + __expf(-u));
}
__device__ __forceinline__ void split2(float a, float b, uint32_t& hi, uint32_t& lo) {
    __nv_bfloat16 ah = __float2bfloat16(a);
    __nv_bfloat16 bh = __float2bfloat16(b);
    __nv_bfloat16 al = __float2bfloat16(a - __bfloat162float(ah));
    __nv_bfloat16 bl = __float2bfloat16(b - __bfloat162float(bh));
    hi = (uint32_t)__bfloat16_as_ushort(ah) | ((uint32_t)__bfloat16_as_ushort(bh) << 16);
    lo = (uint32_t)__bfloat16_as_ushort(al) | ((uint32_t)__bfloat16_as_ushort(bl) << 16);
}

// ---------------- kernel 0: zero counters ----------------
__global__ void zero_cnt_kernel() {
    if (threadIdx.x < NE) g_cnt[threadIdx.x] = 0;
}

// ---------------- kernel 1: gating ----------------
__global__ void gate_kernel(const float* __restrict__ x,
                            const float* __restrict__ Wg,
                            const float* __restrict__ bg) {
    int t = blockIdx.x * 8 + (threadIdx.x >> 5);
    int lane = threadIdx.x & 31;
    const float* xr = x + (size_t)t * HID;

    float acc[NE];
#pragma unroll
    for (int e = 0; e < NE; e++) acc[e] = 0.0f;
    for (int k = lane; k < HID; k += 32) {
        float xv = xr[k];
        const float4* wg4 = (const float4*)(Wg + (size_t)k * NE);
        float4 w0 = wg4[0];
        float4 w1 = wg4[1];
        acc[0] += xv * w0.x; acc[1] += xv * w0.y;
        acc[2] += xv * w0.z; acc[3] += xv * w0.w;
        acc[4] += xv * w1.x; acc[5] += xv * w1.y;
        acc[6] += xv * w1.z; acc[7] += xv * w1.w;
    }
#pragma unroll
    for (int off = 16; off > 0; off >>= 1) {
#pragma unroll
        for (int e = 0; e < NE; e++)
            acc[e] += __shfl_down_sync(0xffffffffu, acc[e], off);
    }
    if (lane == 0) {
        float lg[NE], p[NE];
        float m = -1e30f;
#pragma unroll
        for (int e = 0; e < NE; e++) { lg[e] = acc[e] + bg[e]; m = fmaxf(m, lg[e]); }
        float s = 0.0f;
#pragma unroll
        for (int e = 0; e < NE; e++) { p[e] = expf(lg[e] - m); s += p[e]; }
        float inv = 1.0f / s;
#pragma unroll
        for (int e = 0; e < NE; e++) p[e] *= inv;
        int i1 = 0;
#pragma unroll
        for (int e = 1; e < NE; e++) if (p[e] > p[i1]) i1 = e;
        int i2 = (i1 == 0) ? 1 : 0;
#pragma unroll
        for (int e = 0; e < NE; e++) if (e != i1 && p[e] > p[i2]) i2 = e;

        int pos = atomicAdd(&g_cnt[i1], 1);
        g_list[i1][pos] = t * 2 + 0;
        g_wt[i1][pos]   = p[i1];
        pos = atomicAdd(&g_cnt[i2], 1);
        g_list[i2][pos] = t * 2 + 1;
        g_wt[i2][pos]   = p[i2];
    }
}

// ---------------- kernel 2: padded prefix offsets ----------------
__global__ void offs_kernel() {
    if (threadIdx.x == 0) {
        int o = 0;
#pragma unroll
        for (int e = 0; e < NE; e++) { g_off[e] = o; o += (g_cnt[e] + 127) & ~127; }
    }
}

// ---------------- kernel 3: pack A rows (flat over padded rows) ----------------
__global__ void __launch_bounds__(256)
pack_a_kernel(const float* __restrict__ x) {
    int row = blockIdx.x * 2 + (threadIdx.x >> 7);
    int t4  = threadIdx.x & 127;
    if (row >= ROWCAP) return;

    int e = 0;
#pragma unroll
    for (int i = 1; i < NE; i++) if (row >= g_off[i]) e = i;
    int m = row - g_off[e];

    float4 v = make_float4(0.f, 0.f, 0.f, 0.f);
    if (m < g_cnt[e]) {
        int token = g_list[e][m] >> 1;
        v = *(const float4*)(x + (size_t)token * HID + t4 * 4);
    }
    uint32_t h0, l0, h1, l1;
    split2(v.x, v.y, h0, l0);
    split2(v.z, v.w, h1, l1);
    *(uint2*)(g_a_hi + (size_t)row * HID + t4 * 4) = make_uint2(h0, h1);
    *(uint2*)(g_a_lo + (size_t)row * HID + t4 * 4) = make_uint2(l0, l1);
}

// ---------------- kernel 4: weight transpose + bf16 split ----------------
template <int K, int N>
__device__ __forceinline__ void conv_w_body(const float* __restrict__ W,
                                            __nv_bfloat16* __restrict__ oh,
                                            __nv_bfloat16* __restrict__ ol) {
    __shared__ float t[32][33];
    int e = blockIdx.z;
    const float* Wp = W + (size_t)e * K * N;
    int n0 = blockIdx.x * 32, k0 = blockIdx.y * 32;
    int tx = threadIdx.x, ty = threadIdx.y;
#pragma unroll
    for (int j = ty; j < 32; j += 8)
        t[j][tx] = Wp[(size_t)(k0 + j) * N + n0 + tx];
    __syncthreads();
    size_t ob = (size_t)e * N * K;
#pragma unroll
    for (int j = ty; j < 32; j += 8) {
        float v = t[tx][j];
        __nv_bfloat16 h = __float2bfloat16(v);
        __nv_bfloat16 l = __float2bfloat16(v - __bfloat162float(h));
        oh[ob + (size_t)(n0 + j) * K + k0 + tx] = h;
        ol[ob + (size_t)(n0 + j) * K + k0 + tx] = l;
    }
}
__global__ void conv_w1_kernel(const float* __restrict__ W) {
    conv_w_body<HID, FF>(W, g_w1_hi, g_w1_lo);
}
__global__ void conv_w2_kernel(const float* __restrict__ W) {
    conv_w_body<FF, HID>(W, g_w2_hi, g_w2_lo);
}

// ---------------- HMMA mainloop: 128x256 CTA tile, K-tile 64, 3xBF16 ----------------
// 3-stage cp.async pipeline; 8 warps 4(M)x2(N); warp tile 32x128 via m16n8k16.
// Stage layout: A (16KB) then B (32KB), stride 48KB.
template <int K>
__device__ __forceinline__ void mma_loop(
    const __nv_bfloat16* __restrict__ Ahi, const __nv_bfloat16* __restrict__ Alo,
    const __nv_bfloat16* __restrict__ Bhi, const __nv_bfloat16* __restrict__ Blo,
    uint32_t sm, float acc[2][16][4])
{
    const int tid  = threadIdx.x;
    const int w    = tid >> 5, lane = tid & 31;
    const int wm   = (w & 3) * 32, wn = (w >> 2) * 128;
    const int lrow = lane & 15;
    const int lkof = (lane >> 4) * 8;

    // A loads: 128 rows x 128B, 2 threads/row, 4 x 16B each
    const int alr = tid >> 1;
    const int alc = (tid & 1) * 4;
    uint32_t a_off[4];
#pragma unroll
    for (int i = 0; i < 4; i++) a_off[i] = SWZ(alr * 128 + (alc + i) * 16);
    const size_t a_base = (size_t)alr * K + alc * 8;

    // B loads: 256 rows x 128B, 1 thread/row, 8 x 16B each
    uint32_t b_off[8];
#pragma unroll
    for (int i = 0; i < 8; i++) b_off[i] = SWZ(tid * 128 + i * 16);
    const size_t b_base = (size_t)tid * K;

    constexpr int KT = K / 64;
    constexpr int nT = 3 * KT;

    // prologue: issue tiles 0 and 1
#pragma unroll
    for (int s = 0; s < 2; s++) {
        int seg = s / KT, kt = s - seg * KT;
        const __nv_bfloat16* As = (seg == 2) ? Alo : Ahi;
        const __nv_bfloat16* Bs = (seg == 1) ? Blo : Bhi;
        const __nv_bfloat16* ap = As + a_base + kt * 64;
        const __nv_bfloat16* bp = Bs + b_base + kt * 64;
        uint32_t ab = sm + s * 49152, bb = ab + 16384;
#pragma unroll
        for (int i = 0; i < 4; i++) cp16(ab + a_off[i], ap + i * 8);
#pragma unroll
        for (int i = 0; i < 8; i++) cp16(bb + b_off[i], bp + i * 8);
        asm volatile("cp.async.commit_group;" ::: "memory");
    }

    int buf = 0, buf2 = 2;
    for (int t = 0; t < nT; t++) {
        asm volatile("cp.async.wait_group 1;" ::: "memory");
        __syncthreads();

        int tn = t + 2;
        if (tn < nT) {
            int seg = tn / KT, kt = tn - seg * KT;
            const __nv_bfloat16* As = (seg == 2) ? Alo : Ahi;
            const __nv_bfloat16* Bs = (seg == 1) ? Blo : Bhi;
            const __nv_bfloat16* ap = As + a_base + kt * 64;
            const __nv_bfloat16* bp = Bs + b_base + kt * 64;
            uint32_t ab = sm + buf2 * 49152, bb = ab + 16384;
#pragma unroll
            for (int i = 0; i < 4; i++) cp16(ab + a_off[i], ap + i * 8);
#pragma unroll
            for (int i = 0; i < 8; i++) cp16(bb + b_off[i], bp + i * 8);
        }
        asm volatile("cp.async.commit_group;" ::: "memory");

        uint32_t ab = sm + buf * 49152, bb = ab + 16384;
#pragma unroll
        for (int kk = 0; kk < 4; kk++) {
            const int kb = (kk * 16 + lkof) * 2;
            uint32_t a0[4], a1[4];
            ldsm_x4(a0[0], a0[1], a0[2], a0[3], ab + SWZ((wm + lrow) * 128 + kb));
            ldsm_x4(a1[0], a1[1], a1[2], a1[3], ab + SWZ((wm + 16 + lrow) * 128 + kb));
#pragma unroll
            for (int j = 0; j < 8; j++) {
                uint32_t b0, b1, b2, b3;
                ldsm_x4(b0, b1, b2, b3, bb + SWZ((wn + j * 16 + lrow) * 128 + kb));
                mma16816(acc[0][2 * j],     a0, b0, b2);
                mma16816(acc[1][2 * j],     a1, b0, b2);
                mma16816(acc[0][2 * j + 1], a0, b1, b3);
                mma16816(acc[1][2 * j + 1], a1, b1, b3);
            }
        }
        buf  = (buf == 2) ? 0 : buf + 1;
        buf2 = (buf2 == 2) ? 0 : buf2 + 1;
    }
}

#define SMEM_DYN 147456

// ---------------- kernel 5: grouped GEMM1  h = gelu(x @ W1[e] + b1[e]) ----------------
__global__ void __launch_bounds__(256, 1)
gemm1_mma(const float* __restrict__ b1) {
    const int e   = blockIdx.z;
    const int cnt = g_cnt[e];
    const int m0  = blockIdx.y * 128;
    if (m0 >= cnt) return;
    const int n0  = blockIdx.x * 256;
    const size_t row0 = (size_t)g_off[e] + m0;

    extern __shared__ char dynsm[];
    uint32_t sm = smem_u32(dynsm);

    float acc[2][16][4];
#pragma unroll
    for (int i = 0; i < 2; i++)
#pragma unroll
        for (int j = 0; j < 16; j++)
#pragma unroll
            for (int q = 0; q < 4; q++) acc[i][j][q] = 0.0f;

    mma_loop<HID>(g_a_hi + row0 * HID, g_a_lo + row0 * HID,
                  g_w1_hi + ((size_t)e * FF + n0) * HID,
                  g_w1_lo + ((size_t)e * FF + n0) * HID,
                  sm, acc);

    const int w = threadIdx.x >> 5, lane = threadIdx.x & 31;
    const int wm = (w & 3) * 32, wn = (w >> 2) * 128;
    const float* bias = b1 + (size_t)e * FF + n0;
#pragma unroll
    for (int mi = 0; mi < 2; mi++) {
#pragma unroll
        for (int half = 0; half < 2; half++) {
            int rl = wm + mi * 16 + (lane >> 2) + half * 8;
            size_t hb = (row0 + rl) * FF + n0;
#pragma unroll
            for (int j = 0; j < 16; j++) {
                int c = wn + j * 8 + (lane & 3) * 2;
                float d0 = acc[mi][j][half * 2 + 0] + bias[c];
                float d1 = acc[mi][j][half * 2 + 1] + bias[c + 1];
                uint32_t hi, lo;
                split2(gelu_f(d0), gelu_f(d1), hi, lo);
                *(uint32_t*)(g_h_hi + hb + c) = hi;
                *(uint32_t*)(g_h_lo + hb + c) = lo;
            }
        }
    }
}

// ---------------- kernel 6: grouped GEMM2  out += wgt*(h @ W2[e] + b2[e]) ----------------
__global__ void __launch_bounds__(256, 1)
gemm2_mma(const float* __restrict__ b2, float* __restrict__ out) {
    const int e   = blockIdx.z;
    const int cnt = g_cnt[e];
    const int m0  = blockIdx.y * 128;
    if (m0 >= cnt) return;
    const int n0  = blockIdx.x * 256;
    const size_t row0 = (size_t)g_off[e] + m0;

    extern __shared__ char dynsm[];
    uint32_t sm = smem_u32(dynsm);

    float acc[2][16][4];
#pragma unroll
    for (int i = 0; i < 2; i++)
#pragma unroll
        for (int j = 0; j < 16; j++)
#pragma unroll
            for (int q = 0; q < 4; q++) acc[i][j][q] = 0.0f;

    mma_loop<FF>(g_h_hi + row0 * FF, g_h_lo + row0 * FF,
                 g_w2_hi + ((size_t)e * HID + n0) * FF,
                 g_w2_lo + ((size_t)e * HID + n0) * FF,
                 sm, acc);

    const int w = threadIdx.x >> 5, lane = threadIdx.x & 31;
    const int wm = (w & 3) * 32, wn = (w >> 2) * 128;
    const float* bias = b2 + (size_t)e * HID + n0;
#pragma unroll
    for (int mi = 0; mi < 2; mi++) {
#pragma unroll
        for (int half = 0; half < 2; half++) {
            int m = m0 + wm + mi * 16 + (lane >> 2) + half * 8;
            if (m >= cnt) continue;
            int token = g_list[e][m] >> 1;
            float wgt = g_wt[e][m];
            float* orow = out + (size_t)token * HID + n0;
#pragma unroll
            for (int j = 0; j < 16; j++) {
                int c = wn + j * 8 + (lane & 3) * 2;
                atomicAdd(orow + c,     wgt * (acc[mi][j][half * 2 + 0] + bias[c]));
                atomicAdd(orow + c + 1, wgt * (acc[mi][j][half * 2 + 1] + bias[c + 1]));
            }
        }
    }
}

// ---------------- host launcher ----------------
extern "C" void kernel_launch(void* const* d_in, const int* in_sizes, int n_in,
                              void* d_out, int out_size) {
    const float* x  = (const float*)d_in[0];
    const float* Wg = (const float*)d_in[1];
    const float* bg = (const float*)d_in[2];
    const float* W1 = (const float*)d_in[3];
    const float* b1 = (const float*)d_in[4];
    const float* W2 = (const float*)d_in[5];
    const float* b2 = (const float*)d_in[6];
    float* out = (float*)d_out;

    cudaFuncSetAttribute(gemm1_mma, cudaFuncAttributeMaxDynamicSharedMemorySize, SMEM_DYN);
    cudaFuncSetAttribute(gemm2_mma, cudaFuncAttributeMaxDynamicSharedMemorySize, SMEM_DYN);

    cudaMemsetAsync(out, 0, (size_t)out_size * sizeof(float));
    zero_cnt_kernel<<<1, 32>>>();
    gate_kernel<<<TOK / 8, 256>>>(x, Wg, bg);
    offs_kernel<<<1, 32>>>();
    pack_a_kernel<<<(ROWCAP + 1) / 2, 256>>>(x);
    conv_w1_kernel<<<dim3(FF / 32, HID / 32, NE), dim3(32, 8)>>>(W1);
    conv_w2_kernel<<<dim3(HID / 32, FF / 32, NE), dim3(32, 8)>>>(W2);
    gemm1_mma<<<dim3(FF / 256, TOK / 128, NE), 256, SMEM_DYN>>>(b1);
    gemm2_mma<<<dim3(HID / 256, TOK / 128, NE), 256, SMEM_DYN>>>(b2, out);
}

// round 7
// speedup vs baseline: 1.8355x; 1.8355x over previous
#include <cuda_runtime.h>
#include <cuda_fp16.h>
#include <cstdint>
#include <math.h>

#define TOK 16384
#define HID 512
#define FF  2048
#define NE  8
#define ROWCAP (TOK*2 + NE*128)

typedef unsigned long long u64;

// ---------------- device scratch (no allocations allowed) ----------------
__device__ int   g_cnt[NE];
__device__ int   g_off[NE];
__device__ int   g_list[NE][TOK];
__device__ float g_wt[NE][TOK];

__device__ __half g_a_hi[(size_t)ROWCAP * HID];
__device__ __half g_a_lo[(size_t)ROWCAP * HID];
__device__ __half g_h_hi[(size_t)ROWCAP * FF];
__device__ __half g_h_lo[(size_t)ROWCAP * FF];
__device__ __half g_w1[(size_t)NE * FF * HID];  // [e][n(FF)][k(HID)]
__device__ __half g_w2[(size_t)NE * HID * FF];  // [e][n(HID)][k(FF)]

// ---------------- helpers ----------------
__device__ __forceinline__ uint32_t smem_u32(const void* p) {
    uint32_t a;
    asm("{ .reg .u64 t; cvta.to.shared.u64 t, %1; cvt.u32.u64 %0, t; }" : "=r"(a) : "l"(p));
    return a;
}
#define SWZ(x) ((x) ^ (((x) >> 3) & 0x70))

__device__ __forceinline__ void cp16(uint32_t dst, const void* src) {
    asm volatile("cp.async.cg.shared.global [%0], [%1], 16;" :: "r"(dst), "l"(src));
}
__device__ __forceinline__ void ldsm_x4(uint32_t& r0, uint32_t& r1, uint32_t& r2, uint32_t& r3,
                                        uint32_t addr) {
    asm volatile("ldmatrix.sync.aligned.m8n8.x4.shared.b16 {%0,%1,%2,%3}, [%4];"
                 : "=r"(r0), "=r"(r1), "=r"(r2), "=r"(r3) : "r"(addr));
}
__device__ __forceinline__ void mma16816(float* d, const uint32_t* a, uint32_t b0, uint32_t b1) {
    asm volatile("mma.sync.aligned.m16n8k16.row.col.f32.f16.f16.f32 "
                 "{%0,%1,%2,%3},{%4,%5,%6,%7},{%8,%9},{%0,%1,%2,%3};"
                 : "+f"(d[0]), "+f"(d[1]), "+f"(d[2]), "+f"(d[3])
                 : "r"(a[0]), "r"(a[1]), "r"(a[2]), "r"(a[3]), "r"(b0), "r"(b1));
}
__device__ __forceinline__ float gelu_f(float v) {
    float u = 1.5957691216057308f * (v + 0.044715f * v * v * v);
    return v / (1.0f + __expf(-u));
}
// fp16 hi/lo split of a pair, packed as half2 words
__device__ __forceinline__ void split2h(float a, float b, uint32_t& hi, uint32_t& lo) {
    __half ah = __float2half_rn(a);
    __half bh = __float2half_rn(b);
    __half al = __float2half_rn(a - __half2float(ah));
    __half bl = __float2half_rn(b - __half2float(bh));
    hi = (uint32_t)__half_as_ushort(ah) | ((uint32_t)__half_as_ushort(bh) << 16);
    lo = (uint32_t)__half_as_ushort(al) | ((uint32_t)__half_as_ushort(bl) << 16);
}

// ---------------- kernel 0: zero counters ----------------
__global__ void zero_cnt_kernel() {
    if (threadIdx.x < NE) g_cnt[threadIdx.x] = 0;
}

// ---------------- kernel 1: gating ----------------
__global__ void gate_kernel(const float* __restrict__ x,
                            const float* __restrict__ Wg,
                            const float* __restrict__ bg) {
    int t = blockIdx.x * 8 + (threadIdx.x >> 5);
    int lane = threadIdx.x & 31;
    const float* xr = x + (size_t)t * HID;

    float acc[NE];
#pragma unroll
    for (int e = 0; e < NE; e++) acc[e] = 0.0f;
    for (int k = lane; k < HID; k += 32) {
        float xv = xr[k];
        const float4* wg4 = (const float4*)(Wg + (size_t)k * NE);
        float4 w0 = wg4[0];
        float4 w1 = wg4[1];
        acc[0] += xv * w0.x; acc[1] += xv * w0.y;
        acc[2] += xv * w0.z; acc[3] += xv * w0.w;
        acc[4] += xv * w1.x; acc[5] += xv * w1.y;
        acc[6] += xv * w1.z; acc[7] += xv * w1.w;
    }
#pragma unroll
    for (int off = 16; off > 0; off >>= 1) {
#pragma unroll
        for (int e = 0; e < NE; e++)
            acc[e] += __shfl_down_sync(0xffffffffu, acc[e], off);
    }
    if (lane == 0) {
        float lg[NE], p[NE];
        float m = -1e30f;
#pragma unroll
        for (int e = 0; e < NE; e++) { lg[e] = acc[e] + bg[e]; m = fmaxf(m, lg[e]); }
        float s = 0.0f;
#pragma unroll
        for (int e = 0; e < NE; e++) { p[e] = expf(lg[e] - m); s += p[e]; }
        float inv = 1.0f / s;
#pragma unroll
        for (int e = 0; e < NE; e++) p[e] *= inv;
        int i1 = 0;
#pragma unroll
        for (int e = 1; e < NE; e++) if (p[e] > p[i1]) i1 = e;
        int i2 = (i1 == 0) ? 1 : 0;
#pragma unroll
        for (int e = 0; e < NE; e++) if (e != i1 && p[e] > p[i2]) i2 = e;

        int pos = atomicAdd(&g_cnt[i1], 1);
        g_list[i1][pos] = t * 2 + 0;
        g_wt[i1][pos]   = p[i1];
        pos = atomicAdd(&g_cnt[i2], 1);
        g_list[i2][pos] = t * 2 + 1;
        g_wt[i2][pos]   = p[i2];
    }
}

// ---------------- kernel 2: padded prefix offsets ----------------
__global__ void offs_kernel() {
    if (threadIdx.x == 0) {
        int o = 0;
#pragma unroll
        for (int e = 0; e < NE; e++) { g_off[e] = o; o += (g_cnt[e] + 127) & ~127; }
    }
}

// ---------------- kernel 3: pack A rows (flat over padded rows) ----------------
__global__ void __launch_bounds__(256)
pack_a_kernel(const float* __restrict__ x) {
    int row = blockIdx.x * 2 + (threadIdx.x >> 7);
    int t4  = threadIdx.x & 127;
    if (row >= ROWCAP) return;

    int e = 0;
#pragma unroll
    for (int i = 1; i < NE; i++) if (row >= g_off[i]) e = i;
    int m = row - g_off[e];

    float4 v = make_float4(0.f, 0.f, 0.f, 0.f);
    if (m < g_cnt[e]) {
        int token = g_list[e][m] >> 1;
        v = *(const float4*)(x + (size_t)token * HID + t4 * 4);
    }
    uint32_t h0, l0, h1, l1;
    split2h(v.x, v.y, h0, l0);
    split2h(v.z, v.w, h1, l1);
    *(uint2*)(g_a_hi + (size_t)row * HID + t4 * 4) = make_uint2(h0, h1);
    *(uint2*)(g_a_lo + (size_t)row * HID + t4 * 4) = make_uint2(l0, l1);
}

// ---------------- kernel 4: weight transpose -> fp16 [N][K] ----------------
template <int K, int N>
__device__ __forceinline__ void conv_w_body(const float* __restrict__ W,
                                            __half* __restrict__ oh) {
    __shared__ float t[32][33];
    int e = blockIdx.z;
    const float* Wp = W + (size_t)e * K * N;
    int n0 = blockIdx.x * 32, k0 = blockIdx.y * 32;
    int tx = threadIdx.x, ty = threadIdx.y;
#pragma unroll
    for (int j = ty; j < 32; j += 8)
        t[j][tx] = Wp[(size_t)(k0 + j) * N + n0 + tx];
    __syncthreads();
    size_t ob = (size_t)e * N * K;
#pragma unroll
    for (int j = ty; j < 32; j += 8)
        oh[ob + (size_t)(n0 + j) * K + k0 + tx] = __float2half_rn(t[tx][j]);
}
__global__ void conv_w1_kernel(const float* __restrict__ W) {
    conv_w_body<HID, FF>(W, g_w1);
}
__global__ void conv_w2_kernel(const float* __restrict__ W) {
    conv_w_body<FF, HID>(W, g_w2);
}

// ---------------- HMMA mainloop: 128x128 CTA tile, K-tile 64, 2xFP16 ----------------
// 3-stage cp.async pipeline, one __syncthreads per iteration.
// 8 warps, 4(M) x 2(N); each warp 32x64 via m16n8k16.
template <int K>
__device__ __forceinline__ void mma_loop(
    const __half* __restrict__ Ahi, const __half* __restrict__ Alo,
    const __half* __restrict__ B,
    uint32_t sm, float acc[2][8][4])
{
    const uint32_t smA = sm;
    const uint32_t smB = sm + 49152;

    const int tid  = threadIdx.x;
    const int w    = tid >> 5, lane = tid & 31;
    const int wm   = (w & 3) * 32, wn = (w >> 2) * 64;
    const int lr   = tid >> 1;
    const int lc   = (tid & 1) * 4;
    const int lrow = lane & 15;
    const int lkof = (lane >> 4) * 8;

    uint32_t st_off[4];
#pragma unroll
    for (int i = 0; i < 4; i++) st_off[i] = SWZ(lr * 128 + (lc + i) * 16);

    constexpr int KT = K / 64;
    constexpr int nT = 2 * KT;

    const size_t lbase = (size_t)lr * K + lc * 8;

    // prologue: issue tiles 0 and 1
#pragma unroll
    for (int s = 0; s < 2; s++) {
        int seg = s / KT, kt = s - seg * KT;
        const __half* As = (seg == 1) ? Alo : Ahi;
        const __half* ap = As + lbase + kt * 64;
        const __half* bp = B + lbase + kt * 64;
        uint32_t ab = smA + s * 16384, bb = smB + s * 16384;
#pragma unroll
        for (int i = 0; i < 4; i++) {
            cp16(ab + st_off[i], ap + i * 8);
            cp16(bb + st_off[i], bp + i * 8);
        }
        asm volatile("cp.async.commit_group;" ::: "memory");
    }

    int buf = 0;        // buffer of tile t
    int buf2 = 2;       // buffer of tile t+2
    for (int t = 0; t < nT; t++) {
        asm volatile("cp.async.wait_group 1;" ::: "memory");
        __syncthreads();

        int tn = t + 2;
        if (tn < nT) {
            int seg = tn / KT, kt = tn - seg * KT;
            const __half* As = (seg == 1) ? Alo : Ahi;
            const __half* ap = As + lbase + kt * 64;
            const __half* bp = B + lbase + kt * 64;
            uint32_t ab = smA + buf2 * 16384, bb = smB + buf2 * 16384;
#pragma unroll
            for (int i = 0; i < 4; i++) {
                cp16(ab + st_off[i], ap + i * 8);
                cp16(bb + st_off[i], bp + i * 8);
            }
        }
        asm volatile("cp.async.commit_group;" ::: "memory");

        uint32_t ab = smA + buf * 16384, bb = smB + buf * 16384;
#pragma unroll
        for (int kk = 0; kk < 4; kk++) {
            const int kb = (kk * 16 + lkof) * 2;
            uint32_t a0[4], a1[4], B0[4], B1[4], B2[4], B3[4];
            ldsm_x4(a0[0], a0[1], a0[2], a0[3], ab + SWZ((wm + lrow) * 128 + kb));
            ldsm_x4(a1[0], a1[1], a1[2], a1[3], ab + SWZ((wm + 16 + lrow) * 128 + kb));
            ldsm_x4(B0[0], B0[1], B0[2], B0[3], bb + SWZ((wn + lrow) * 128 + kb));
            ldsm_x4(B1[0], B1[1], B1[2], B1[3], bb + SWZ((wn + 16 + lrow) * 128 + kb));
            ldsm_x4(B2[0], B2[1], B2[2], B2[3], bb + SWZ((wn + 32 + lrow) * 128 + kb));
            ldsm_x4(B3[0], B3[1], B3[2], B3[3], bb + SWZ((wn + 48 + lrow) * 128 + kb));

            mma16816(acc[0][0], a0, B0[0], B0[2]);
            mma16816(acc[1][0], a1, B0[0], B0[2]);
            mma16816(acc[0][1], a0, B0[1], B0[3]);
            mma16816(acc[1][1], a1, B0[1], B0[3]);
            mma16816(acc[0][2], a0, B1[0], B1[2]);
            mma16816(acc[1][2], a1, B1[0], B1[2]);
            mma16816(acc[0][3], a0, B1[1], B1[3]);
            mma16816(acc[1][3], a1, B1[1], B1[3]);
            mma16816(acc[0][4], a0, B2[0], B2[2]);
            mma16816(acc[1][4], a1, B2[0], B2[2]);
            mma16816(acc[0][5], a0, B2[1], B2[3]);
            mma16816(acc[1][5], a1, B2[1], B2[3]);
            mma16816(acc[0][6], a0, B3[0], B3[2]);
            mma16816(acc[1][6], a1, B3[0], B3[2]);
            mma16816(acc[0][7], a0, B3[1], B3[3]);
            mma16816(acc[1][7], a1, B3[1], B3[3]);
        }
        buf  = (buf == 2) ? 0 : buf + 1;
        buf2 = (buf2 == 2) ? 0 : buf2 + 1;
    }
}

#define SMEM_DYN 98304

// ---------------- kernel 5: grouped GEMM1  h = gelu(x @ W1[e] + b1[e]) ----------------
__global__ void __launch_bounds__(256, 2)
gemm1_mma(const float* __restrict__ b1) {
    const int e   = blockIdx.z;
    const int cnt = g_cnt[e];
    const int m0  = blockIdx.y * 128;
    if (m0 >= cnt) return;
    const int n0  = blockIdx.x * 128;
    const size_t row0 = (size_t)g_off[e] + m0;

    extern __shared__ char dynsm[];
    uint32_t sm = smem_u32(dynsm);

    float acc[2][8][4];
#pragma unroll
    for (int i = 0; i < 2; i++)
#pragma unroll
        for (int j = 0; j < 8; j++)
#pragma unroll
            for (int q = 0; q < 4; q++) acc[i][j][q] = 0.0f;

    mma_loop<HID>(g_a_hi + row0 * HID, g_a_lo + row0 * HID,
                  g_w1 + ((size_t)e * FF + n0) * HID,
                  sm, acc);

    const int w = threadIdx.x >> 5, lane = threadIdx.x & 31;
    const int wm = (w & 3) * 32, wn = (w >> 2) * 64;
    const float* bias = b1 + (size_t)e * FF + n0;
#pragma unroll
    for (int mi = 0; mi < 2; mi++) {
#pragma unroll
        for (int half = 0; half < 2; half++) {
            int rl = wm + mi * 16 + (lane >> 2) + half * 8;
            size_t hb = (row0 + rl) * FF + n0;
#pragma unroll
            for (int j = 0; j < 8; j++) {
                int c = wn + j * 8 + (lane & 3) * 2;
                float d0 = acc[mi][j][half * 2 + 0] + bias[c];
                float d1 = acc[mi][j][half * 2 + 1] + bias[c + 1];
                uint32_t hi, lo;
                split2h(gelu_f(d0), gelu_f(d1), hi, lo);
                *(uint32_t*)(g_h_hi + hb + c) = hi;
                *(uint32_t*)(g_h_lo + hb + c) = lo;
            }
        }
    }
}

// ---------------- kernel 6: grouped GEMM2  out += wgt*(h @ W2[e] + b2[e]) ----------------
__global__ void __launch_bounds__(256, 2)
gemm2_mma(const float* __restrict__ b2, float* __restrict__ out) {
    const int e   = blockIdx.z;
    const int cnt = g_cnt[e];
    const int m0  = blockIdx.y * 128;
    if (m0 >= cnt) return;
    const int n0  = blockIdx.x * 128;
    const size_t row0 = (size_t)g_off[e] + m0;

    extern __shared__ char dynsm[];
    uint32_t sm = smem_u32(dynsm);

    float acc[2][8][4];
#pragma unroll
    for (int i = 0; i < 2; i++)
#pragma unroll
        for (int j = 0; j < 8; j++)
#pragma unroll
            for (int q = 0; q < 4; q++) acc[i][j][q] = 0.0f;

    mma_loop<FF>(g_h_hi + row0 * FF, g_h_lo + row0 * FF,
                 g_w2 + ((size_t)e * HID + n0) * FF,
                 sm, acc);

    const int w = threadIdx.x >> 5, lane = threadIdx.x & 31;
    const int wm = (w & 3) * 32, wn = (w >> 2) * 64;
    const float* bias = b2 + (size_t)e * HID + n0;
#pragma unroll
    for (int mi = 0; mi < 2; mi++) {
#pragma unroll
        for (int half = 0; half < 2; half++) {
            int m = m0 + wm + mi * 16 + (lane >> 2) + half * 8;
            if (m >= cnt) continue;
            int token = g_list[e][m] >> 1;
            float wgt = g_wt[e][m];
            float* orow = out + (size_t)token * HID + n0;
#pragma unroll
            for (int j = 0; j < 8; j++) {
                int c = wn + j * 8 + (lane & 3) * 2;
                atomicAdd(orow + c,     wgt * (acc[mi][j][half * 2 + 0] + bias[c]));
                atomicAdd(orow + c + 1, wgt * (acc[mi][j][half * 2 + 1] + bias[c + 1]));
            }
        }
    }
}

// ---------------- host launcher ----------------
extern "C" void kernel_launch(void* const* d_in, const int* in_sizes, int n_in,
                              void* d_out, int out_size) {
    const float* x  = (const float*)d_in[0];
    const float* Wg = (const float*)d_in[1];
    const float* bg = (const float*)d_in[2];
    const float* W1 = (const float*)d_in[3];
    const float* b1 = (const float*)d_in[4];
    const float* W2 = (const float*)d_in[5];
    const float* b2 = (const float*)d_in[6];
    float* out = (float*)d_out;

    cudaFuncSetAttribute(gemm1_mma, cudaFuncAttributeMaxDynamicSharedMemorySize, SMEM_DYN);
    cudaFuncSetAttribute(gemm2_mma, cudaFuncAttributeMaxDynamicSharedMemorySize, SMEM_DYN);

    cudaMemsetAsync(out, 0, (size_t)out_size * sizeof(float));
    zero_cnt_kernel<<<1, 32>>>();
    gate_kernel<<<TOK / 8, 256>>>(x, Wg, bg);
    offs_kernel<<<1, 32>>>();
    pack_a_kernel<<<(ROWCAP + 1) / 2, 256>>>(x);
    conv_w1_kernel<<<dim3(FF / 32, HID / 32, NE), dim3(32, 8)>>>(W1);
    conv_w2_kernel<<<dim3(HID / 32, FF / 32, NE), dim3(32, 8)>>>(W2);
    gemm1_mma<<<dim3(FF / 128, TOK / 128, NE), 256, SMEM_DYN>>>(b1);
    gemm2_mma<<<dim3(HID / 128, TOK / 128, NE), 256, SMEM_DYN>>>(b2, out);
}

// round 8
// speedup vs baseline: 3.1441x; 1.7129x over previous
#include <cuda_runtime.h>
#include <cuda_fp16.h>
#include <cstdint>
#include <math.h>

#define TOK 16384
#define HID 512
#define FF  2048
#define NE  8
#define ROWCAP (TOK*2 + NE*128)

typedef unsigned long long u64;

// ---------------- device scratch (no allocations allowed) ----------------
__device__ int   g_cnt[NE];
__device__ int   g_off[NE];
__device__ int   g_list[NE][TOK];
__device__ float g_wt[NE][TOK];

__device__ __half g_a[(size_t)ROWCAP * HID];
__device__ __half g_h[(size_t)ROWCAP * FF];
__device__ __half g_w1[(size_t)NE * FF * HID];  // [e][n(FF)][k(HID)]
__device__ __half g_w2[(size_t)NE * HID * FF];  // [e][n(HID)][k(FF)]

// ---------------- helpers ----------------
__device__ __forceinline__ uint32_t smem_u32(const void* p) {
    uint32_t a;
    asm("{ .reg .u64 t; cvta.to.shared.u64 t, %1; cvt.u32.u64 %0, t; }" : "=r"(a) : "l"(p));
    return a;
}
#define SWZ(x) ((x) ^ (((x) >> 3) & 0x70))

__device__ __forceinline__ void cp16(uint32_t dst, const void* src) {
    asm volatile("cp.async.cg.shared.global [%0], [%1], 16;" :: "r"(dst), "l"(src));
}
__device__ __forceinline__ void ldsm_x4(uint32_t& r0, uint32_t& r1, uint32_t& r2, uint32_t& r3,
                                        uint32_t addr) {
    asm volatile("ldmatrix.sync.aligned.m8n8.x4.shared.b16 {%0,%1,%2,%3}, [%4];"
                 : "=r"(r0), "=r"(r1), "=r"(r2), "=r"(r3) : "r"(addr));
}
__device__ __forceinline__ void mma16816(float* d, const uint32_t* a, uint32_t b0, uint32_t b1) {
    asm volatile("mma.sync.aligned.m16n8k16.row.col.f32.f16.f16.f32 "
                 "{%0,%1,%2,%3},{%4,%5,%6,%7},{%8,%9},{%0,%1,%2,%3};"
                 : "+f"(d[0]), "+f"(d[1]), "+f"(d[2]), "+f"(d[3])
                 : "r"(a[0]), "r"(a[1]), "r"(a[2]), "r"(a[3]), "r"(b0), "r"(b1));
}
__device__ __forceinline__ float gelu_f(float v) {
    float u = 1.5957691216057308f * (v + 0.044715f * v * v * v);
    return v / (1.0f + __expf(-u));
}
__device__ __forceinline__ uint32_t pack_h2(float a, float b) {
    __half ah = __float2half_rn(a);
    __half bh = __float2half_rn(b);
    return (uint32_t)__half_as_ushort(ah) | ((uint32_t)__half_as_ushort(bh) << 16);
}

// ---------------- kernel 0: zero counters ----------------
__global__ void zero_cnt_kernel() {
    if (threadIdx.x < NE) g_cnt[threadIdx.x] = 0;
}

// ---------------- kernel 1: gating ----------------
__global__ void gate_kernel(const float* __restrict__ x,
                            const float* __restrict__ Wg,
                            const float* __restrict__ bg) {
    int t = blockIdx.x * 8 + (threadIdx.x >> 5);
    int lane = threadIdx.x & 31;
    const float* xr = x + (size_t)t * HID;

    float acc[NE];
#pragma unroll
    for (int e = 0; e < NE; e++) acc[e] = 0.0f;
    for (int k = lane; k < HID; k += 32) {
        float xv = xr[k];
        const float4* wg4 = (const float4*)(Wg + (size_t)k * NE);
        float4 w0 = wg4[0];
        float4 w1 = wg4[1];
        acc[0] += xv * w0.x; acc[1] += xv * w0.y;
        acc[2] += xv * w0.z; acc[3] += xv * w0.w;
        acc[4] += xv * w1.x; acc[5] += xv * w1.y;
        acc[6] += xv * w1.z; acc[7] += xv * w1.w;
    }
#pragma unroll
    for (int off = 16; off > 0; off >>= 1) {
#pragma unroll
        for (int e = 0; e < NE; e++)
            acc[e] += __shfl_down_sync(0xffffffffu, acc[e], off);
    }
    if (lane == 0) {
        float lg[NE], p[NE];
        float m = -1e30f;
#pragma unroll
        for (int e = 0; e < NE; e++) { lg[e] = acc[e] + bg[e]; m = fmaxf(m, lg[e]); }
        float s = 0.0f;
#pragma unroll
        for (int e = 0; e < NE; e++) { p[e] = expf(lg[e] - m); s += p[e]; }
        float inv = 1.0f / s;
#pragma unroll
        for (int e = 0; e < NE; e++) p[e] *= inv;
        int i1 = 0;
#pragma unroll
        for (int e = 1; e < NE; e++) if (p[e] > p[i1]) i1 = e;
        int i2 = (i1 == 0) ? 1 : 0;
#pragma unroll
        for (int e = 0; e < NE; e++) if (e != i1 && p[e] > p[i2]) i2 = e;

        int pos = atomicAdd(&g_cnt[i1], 1);
        g_list[i1][pos] = t * 2 + 0;
        g_wt[i1][pos]   = p[i1];
        pos = atomicAdd(&g_cnt[i2], 1);
        g_list[i2][pos] = t * 2 + 1;
        g_wt[i2][pos]   = p[i2];
    }
}

// ---------------- kernel 2: padded prefix offsets ----------------
__global__ void offs_kernel() {
    if (threadIdx.x == 0) {
        int o = 0;
#pragma unroll
        for (int e = 0; e < NE; e++) { g_off[e] = o; o += (g_cnt[e] + 127) & ~127; }
    }
}

// ---------------- kernel 3: pack A rows (flat over padded rows) ----------------
__global__ void __launch_bounds__(256)
pack_a_kernel(const float* __restrict__ x) {
    int row = blockIdx.x * 2 + (threadIdx.x >> 7);
    int t4  = threadIdx.x & 127;
    if (row >= ROWCAP) return;

    int e = 0;
#pragma unroll
    for (int i = 1; i < NE; i++) if (row >= g_off[i]) e = i;
    int m = row - g_off[e];

    float4 v = make_float4(0.f, 0.f, 0.f, 0.f);
    if (m < g_cnt[e]) {
        int token = g_list[e][m] >> 1;
        v = *(const float4*)(x + (size_t)token * HID + t4 * 4);
    }
    *(uint2*)(g_a + (size_t)row * HID + t4 * 4) =
        make_uint2(pack_h2(v.x, v.y), pack_h2(v.z, v.w));
}

// ---------------- kernel 4: weight transpose -> fp16 [N][K] ----------------
template <int K, int N>
__device__ __forceinline__ void conv_w_body(const float* __restrict__ W,
                                            __half* __restrict__ oh) {
    __shared__ float t[32][33];
    int e = blockIdx.z;
    const float* Wp = W + (size_t)e * K * N;
    int n0 = blockIdx.x * 32, k0 = blockIdx.y * 32;
    int tx = threadIdx.x, ty = threadIdx.y;
#pragma unroll
    for (int j = ty; j < 32; j += 8)
        t[j][tx] = Wp[(size_t)(k0 + j) * N + n0 + tx];
    __syncthreads();
    size_t ob = (size_t)e * N * K;
#pragma unroll
    for (int j = ty; j < 32; j += 8)
        oh[ob + (size_t)(n0 + j) * K + k0 + tx] = __float2half_rn(t[tx][j]);
}
__global__ void conv_w1_kernel(const float* __restrict__ W) {
    conv_w_body<HID, FF>(W, g_w1);
}
__global__ void conv_w2_kernel(const float* __restrict__ W) {
    conv_w_body<FF, HID>(W, g_w2);
}

// ---------------- HMMA mainloop: 128x128 CTA tile, K-tile 64, single fp16 pass ----------------
// 3-stage cp.async pipeline, one __syncthreads per iteration.
// 8 warps, 4(M) x 2(N); each warp 32x64 via m16n8k16.
template <int K>
__device__ __forceinline__ void mma_loop(
    const __half* __restrict__ A, const __half* __restrict__ B,
    uint32_t sm, float acc[2][8][4])
{
    const uint32_t smA = sm;
    const uint32_t smB = sm + 49152;

    const int tid  = threadIdx.x;
    const int w    = tid >> 5, lane = tid & 31;
    const int wm   = (w & 3) * 32, wn = (w >> 2) * 64;
    const int lr   = tid >> 1;
    const int lc   = (tid & 1) * 4;
    const int lrow = lane & 15;
    const int lkof = (lane >> 4) * 8;

    uint32_t st_off[4];
#pragma unroll
    for (int i = 0; i < 4; i++) st_off[i] = SWZ(lr * 128 + (lc + i) * 16);

    constexpr int nT = K / 64;
    const size_t lbase = (size_t)lr * K + lc * 8;

    // prologue: issue tiles 0 and 1
#pragma unroll
    for (int s = 0; s < 2; s++) {
        const __half* ap = A + lbase + s * 64;
        const __half* bp = B + lbase + s * 64;
        uint32_t ab = smA + s * 16384, bb = smB + s * 16384;
#pragma unroll
        for (int i = 0; i < 4; i++) {
            cp16(ab + st_off[i], ap + i * 8);
            cp16(bb + st_off[i], bp + i * 8);
        }
        asm volatile("cp.async.commit_group;" ::: "memory");
    }

    int buf = 0, buf2 = 2;
    for (int t = 0; t < nT; t++) {
        asm volatile("cp.async.wait_group 1;" ::: "memory");
        __syncthreads();

        int tn = t + 2;
        if (tn < nT) {
            const __half* ap = A + lbase + tn * 64;
            const __half* bp = B + lbase + tn * 64;
            uint32_t ab = smA + buf2 * 16384, bb = smB + buf2 * 16384;
#pragma unroll
            for (int i = 0; i < 4; i++) {
                cp16(ab + st_off[i], ap + i * 8);
                cp16(bb + st_off[i], bp + i * 8);
            }
        }
        asm volatile("cp.async.commit_group;" ::: "memory");

        uint32_t ab = smA + buf * 16384, bb = smB + buf * 16384;
#pragma unroll
        for (int kk = 0; kk < 4; kk++) {
            const int kb = (kk * 16 + lkof) * 2;
            uint32_t a0[4], a1[4], B0[4], B1[4], B2[4], B3[4];
            ldsm_x4(a0[0], a0[1], a0[2], a0[3], ab + SWZ((wm + lrow) * 128 + kb));
            ldsm_x4(a1[0], a1[1], a1[2], a1[3], ab + SWZ((wm + 16 + lrow) * 128 + kb));
            ldsm_x4(B0[0], B0[1], B0[2], B0[3], bb + SWZ((wn + lrow) * 128 + kb));
            ldsm_x4(B1[0], B1[1], B1[2], B1[3], bb + SWZ((wn + 16 + lrow) * 128 + kb));
            ldsm_x4(B2[0], B2[1], B2[2], B2[3], bb + SWZ((wn + 32 + lrow) * 128 + kb));
            ldsm_x4(B3[0], B3[1], B3[2], B3[3], bb + SWZ((wn + 48 + lrow) * 128 + kb));

            mma16816(acc[0][0], a0, B0[0], B0[2]);
            mma16816(acc[1][0], a1, B0[0], B0[2]);
            mma16816(acc[0][1], a0, B0[1], B0[3]);
            mma16816(acc[1][1], a1, B0[1], B0[3]);
            mma16816(acc[0][2], a0, B1[0], B1[2]);
            mma16816(acc[1][2], a1, B1[0], B1[2]);
            mma16816(acc[0][3], a0, B1[1], B1[3]);
            mma16816(acc[1][3], a1, B1[1], B1[3]);
            mma16816(acc[0][4], a0, B2[0], B2[2]);
            mma16816(acc[1][4], a1, B2[0], B2[2]);
            mma16816(acc[0][5], a0, B2[1], B2[3]);
            mma16816(acc[1][5], a1, B2[1], B2[3]);
            mma16816(acc[0][6], a0, B3[0], B3[2]);
            mma16816(acc[1][6], a1, B3[0], B3[2]);
            mma16816(acc[0][7], a0, B3[1], B3[3]);
            mma16816(acc[1][7], a1, B3[1], B3[3]);
        }
        buf  = (buf == 2) ? 0 : buf + 1;
        buf2 = (buf2 == 2) ? 0 : buf2 + 1;
    }
}

#define SMEM_DYN 98304

// ---------------- kernel 5: grouped GEMM1  h = gelu(x @ W1[e] + b1[e]) ----------------
__global__ void __launch_bounds__(256, 2)
gemm1_mma(const float* __restrict__ b1) {
    const int e   = blockIdx.z;
    const int cnt = g_cnt[e];
    const int m0  = blockIdx.y * 128;
    if (m0 >= cnt) return;
    const int n0  = blockIdx.x * 128;
    const size_t row0 = (size_t)g_off[e] + m0;

    extern __shared__ char dynsm[];
    uint32_t sm = smem_u32(dynsm);

    float acc[2][8][4];
#pragma unroll
    for (int i = 0; i < 2; i++)
#pragma unroll
        for (int j = 0; j < 8; j++)
#pragma unroll
            for (int q = 0; q < 4; q++) acc[i][j][q] = 0.0f;

    mma_loop<HID>(g_a + row0 * HID,
                  g_w1 + ((size_t)e * FF + n0) * HID,
                  sm, acc);

    const int w = threadIdx.x >> 5, lane = threadIdx.x & 31;
    const int wm = (w & 3) * 32, wn = (w >> 2) * 64;
    const float* bias = b1 + (size_t)e * FF + n0;
#pragma unroll
    for (int mi = 0; mi < 2; mi++) {
#pragma unroll
        for (int half = 0; half < 2; half++) {
            int rl = wm + mi * 16 + (lane >> 2) + half * 8;
            size_t hb = (row0 + rl) * FF + n0;
#pragma unroll
            for (int j = 0; j < 8; j++) {
                int c = wn + j * 8 + (lane & 3) * 2;
                float d0 = acc[mi][j][half * 2 + 0] + bias[c];
                float d1 = acc[mi][j][half * 2 + 1] + bias[c + 1];
                *(uint32_t*)(g_h + hb + c) = pack_h2(gelu_f(d0), gelu_f(d1));
            }
        }
    }
}

// ---------------- kernel 6: grouped GEMM2  out += wgt*(h @ W2[e] + b2[e]) ----------------
__global__ void __launch_bounds__(256, 2)
gemm2_mma(const float* __restrict__ b2, float* __restrict__ out) {
    const int e   = blockIdx.z;
    const int cnt = g_cnt[e];
    const int m0  = blockIdx.y * 128;
    if (m0 >= cnt) return;
    const int n0  = blockIdx.x * 128;
    const size_t row0 = (size_t)g_off[e] + m0;

    extern __shared__ char dynsm[];
    uint32_t sm = smem_u32(dynsm);

    float acc[2][8][4];
#pragma unroll
    for (int i = 0; i < 2; i++)
#pragma unroll
        for (int j = 0; j < 8; j++)
#pragma unroll
            for (int q = 0; q < 4; q++) acc[i][j][q] = 0.0f;

    mma_loop<FF>(g_h + row0 * FF,
                 g_w2 + ((size_t)e * HID + n0) * FF,
                 sm, acc);

    const int w = threadIdx.x >> 5, lane = threadIdx.x & 31;
    const int wm = (w & 3) * 32, wn = (w >> 2) * 64;
    const float* bias = b2 + (size_t)e * HID + n0;
#pragma unroll
    for (int mi = 0; mi < 2; mi++) {
#pragma unroll
        for (int half = 0; half < 2; half++) {
            int m = m0 + wm + mi * 16 + (lane >> 2) + half * 8;
            if (m >= cnt) continue;
            int token = g_list[e][m] >> 1;
            float wgt = g_wt[e][m];
            float* orow = out + (size_t)token * HID + n0;
#pragma unroll
            for (int j = 0; j < 8; j++) {
                int c = wn + j * 8 + (lane & 3) * 2;
                atomicAdd(orow + c,     wgt * (acc[mi][j][half * 2 + 0] + bias[c]));
                atomicAdd(orow + c + 1, wgt * (acc[mi][j][half * 2 + 1] + bias[c + 1]));
            }
        }
    }
}

// ---------------- host launcher ----------------
extern "C" void kernel_launch(void* const* d_in, const int* in_sizes, int n_in,
                              void* d_out, int out_size) {
    const float* x  = (const float*)d_in[0];
    const float* Wg = (const float*)d_in[1];
    const float* bg = (const float*)d_in[2];
    const float* W1 = (const float*)d_in[3];
    const float* b1 = (const float*)d_in[4];
    const float* W2 = (const float*)d_in[5];
    const float* b2 = (const float*)d_in[6];
    float* out = (float*)d_out;

    cudaFuncSetAttribute(gemm1_mma, cudaFuncAttributeMaxDynamicSharedMemorySize, SMEM_DYN);
    cudaFuncSetAttribute(gemm2_mma, cudaFuncAttributeMaxDynamicSharedMemorySize, SMEM_DYN);

    cudaMemsetAsync(out, 0, (size_t)out_size * sizeof(float));
    zero_cnt_kernel<<<1, 32>>>();
    gate_kernel<<<TOK / 8, 256>>>(x, Wg, bg);
    offs_kernel<<<1, 32>>>();
    pack_a_kernel<<<(ROWCAP + 1) / 2, 256>>>(x);
    conv_w1_kernel<<<dim3(FF / 32, HID / 32, NE), dim3(32, 8)>>>(W1);
    conv_w2_kernel<<<dim3(HID / 32, FF / 32, NE), dim3(32, 8)>>>(W2);
    gemm1_mma<<<dim3(FF / 128, TOK / 128, NE), 256, SMEM_DYN>>>(b1);
    gemm2_mma<<<dim3(HID / 128, TOK / 128, NE), 256, SMEM_DYN>>>(b2, out);
}